// round 7
// baseline (speedup 1.0000x reference)
#include <cuda_runtime.h>

// ---------------------------------------------------------------------------
// Problem constants
// ---------------------------------------------------------------------------
#define TT   256          // time frames (h)
#define PP   88           // pitches (w)
#define CC   128          // channels
#define NH   4            // heads
#define HD   32           // head dim
#define WIN  25           // neighborhood window
#define M_ROWS (TT*PP)    // 22528
#define KCAT 144          // padded concat K (128 + 2 + 1 -> pad to 144)
#define BT   4            // t-rows per attention block (= queries per thread)

#define QSCALE 0.17677669529663689f   // 32^-0.5

typedef unsigned long long ull;

// ---- f32x2 packed helpers (sm_103a FFMA2 is PTX-only) ----------------------
__device__ __forceinline__ ull pk2(float lo, float hi) {
    ull r; asm("mov.b64 %0,{%1,%2};" : "=l"(r) : "f"(lo), "f"(hi)); return r;
}
__device__ __forceinline__ ull dup2(float x) { return pk2(x, x); }
__device__ __forceinline__ ull fma2(ull a, ull b, ull c) {
    ull d; asm("fma.rn.f32x2 %0,%1,%2,%3;" : "=l"(d) : "l"(a), "l"(b), "l"(c)); return d;
}
__device__ __forceinline__ void upk2(ull v, float& lo, float& hi) {
    asm("mov.b64 {%0,%1},%2;" : "=f"(lo), "=f"(hi) : "l"(v));
}

// ---------------------------------------------------------------------------
// Scratch (static device globals -- no allocation allowed)
// ---------------------------------------------------------------------------
__device__ float g_Y[M_ROWS * CC];
__device__ float g_QKV[3 * NH * M_ROWS * HD];   // [i3][head][m][hd]
__device__ float g_AO[M_ROWS * CC];
__device__ float g_WtLin[KCAT * CC];            // [k][n]
__device__ float g_WtQkv[CC * 3 * CC];          // [k][n] n<384
__device__ float g_WtProj[CC * CC];             // [k][n]

// ---------------------------------------------------------------------------
// Prep kernel: transpose weights to [k][n], zero-pad k
// ---------------------------------------------------------------------------
__global__ void transpose_w_kernel(float* __restrict__ dst, const float* __restrict__ src,
                                   int Ksrc, int Kdst, int N) {
    int idx = blockIdx.x * 256 + threadIdx.x;
    if (idx >= Kdst * N) return;
    int k = idx / N, n = idx - k * N;
    dst[idx] = (k < Ksrc) ? src[n * Ksrc + k] : 0.f;
}

// ---------------------------------------------------------------------------
// Tiled SGEMM with f32x2 FMAs:  C[m][n] = sum_k A[m][k] * Bt[k][n] + bias[n]
// BM = BN = 128, BK = 16, 256 threads, 8x8 micro-tile (held as 8x4 f32x2).
// MODE 0: fusion  (A is the virtual concat [x | cond | mask | 0-pad], relu)
// MODE 1: qkv     (scatter into g_QKV layout, scale q by HD^-0.5)
// MODE 2: proj    (write row-major CC)
// ---------------------------------------------------------------------------
template <int MODE>
__global__ void __launch_bounds__(256) gemm_kernel(const float* __restrict__ A, int lda,
                                                   const float* __restrict__ Bt, int ldb,
                                                   const float* __restrict__ bias,
                                                   float* __restrict__ C, int K,
                                                   const float* __restrict__ cond,
                                                   const float* __restrict__ maskp) {
    __shared__ float As[16][132];   // [k][m], padded
    __shared__ float Bs[16][128];   // [k][n]

    const int m0 = blockIdx.y * 128;
    const int n0 = blockIdx.x * 128;
    const int tid = threadIdx.x;
    const int tx = tid & 15;
    const int ty = tid >> 4;

    ull acc2[8][4];
#pragma unroll
    for (int i = 0; i < 8; i++)
#pragma unroll
        for (int j = 0; j < 4; j++) acc2[i][j] = 0ull;

    for (int k0 = 0; k0 < K; k0 += 16) {
#pragma unroll
        for (int ii = 0; ii < 2; ii++) {
            int lin = tid + ii * 256;
            int r  = lin >> 2;            // 0..127
            int c4 = (lin & 3) * 4;       // 0,4,8,12
            int row = m0 + r;
            float4 a4;
            if (MODE == 0) {
                // virtual concat row: [x(128) | cond(2) | mask(1) | zeros]
                if (k0 < CC) {
                    a4 = *(const float4*)(A + row * CC + k0 + c4);
                } else if (c4 == 0) {
                    a4 = make_float4(cond[row * 2], cond[row * 2 + 1], maskp[row], 0.f);
                } else {
                    a4 = make_float4(0.f, 0.f, 0.f, 0.f);
                }
            } else {
                a4 = *(const float4*)(A + row * lda + k0 + c4);
            }
            As[c4 + 0][r] = a4.x; As[c4 + 1][r] = a4.y;
            As[c4 + 2][r] = a4.z; As[c4 + 3][r] = a4.w;
            int rb = lin >> 5;            // 0..15
            int cb = (lin & 31) * 4;      // 0..124
            *(float4*)&Bs[rb][cb] = *(const float4*)(Bt + (k0 + rb) * ldb + n0 + cb);
        }
        __syncthreads();
#pragma unroll
        for (int kk = 0; kk < 16; kk++) {
            float a[8];
            *(float4*)&a[0] = *(const float4*)&As[kk][ty * 8];
            *(float4*)&a[4] = *(const float4*)&As[kk][ty * 8 + 4];
            const ull* bp = (const ull*)&Bs[kk][tx * 8];
            ull b2[4] = { bp[0], bp[1], bp[2], bp[3] };
#pragma unroll
            for (int i = 0; i < 8; i++) {
                ull ad = dup2(a[i]);
#pragma unroll
                for (int j = 0; j < 4; j++)
                    acc2[i][j] = fma2(ad, b2[j], acc2[i][j]);
            }
        }
        __syncthreads();
    }

    // epilogue
#pragma unroll
    for (int i = 0; i < 8; i++) {
        int m = m0 + ty * 8 + i;
#pragma unroll
        for (int j4 = 0; j4 < 2; j4++) {
            int nbase = n0 + tx * 8 + j4 * 4;
            float vv[4];
            upk2(acc2[i][j4 * 2 + 0], vv[0], vv[1]);
            upk2(acc2[i][j4 * 2 + 1], vv[2], vv[3]);
#pragma unroll
            for (int j = 0; j < 4; j++) {
                float t = vv[j] + bias[nbase + j];
                if (MODE == 0) t = fmaxf(t, 0.f);
                if (MODE == 1 && nbase < 128) t *= QSCALE;
                vv[j] = t;
            }
            if (MODE == 1) {
                int i3   = nbase >> 7;
                int head = (nbase >> 5) & 3;
                int hd   = nbase & 31;
                *(float4*)&C[((i3 * NH + head) * M_ROWS + m) * HD + hd] = *(float4*)vv;
            } else {
                *(float4*)&C[m * CC + nbase] = *(float4*)vv;
            }
        }
    }
}

// ---------------------------------------------------------------------------
// Neighborhood attention: one head per block, 88 threads, each thread owns the
// 4 queries (t0..t0+3, p). Every K/V LDS.64 (window-pair packed) feeds 4 fma2
// -> smem bytes and LDS instructions per query are HALF of the 2-query scheme.
// Max-free softmax (scores tiny, no overflow). Window slab [x0, x0+25] (26
// even-aligned cols = 13 f32x2 pairs) processed in two halves (7+6 pairs) to
// keep live score registers at 56 while o[4][32] stays resident.
// ---------------------------------------------------------------------------
__global__ void __launch_bounds__(88, 2) attn_kernel(const float* __restrict__ QKVbuf,
                                                     const float* __restrict__ rpb,
                                                     float* __restrict__ AO) {
    __shared__ float Ksh[HD][90];   // [d][p], 8B-aligned rows, conflict-free
    __shared__ float Vsh[HD][90];
    __shared__ float Rpb[49 * 49 + 2];   // +2: speculated masked reads stay in-bounds

    const int h  = blockIdx.y;
    const int t0 = blockIdx.x * BT;
    const int p  = threadIdx.x;          // 0..87

    const float* Qg = QKVbuf;
    const float* Kg = QKVbuf + NH * M_ROWS * HD;
    const float* Vg = QKVbuf + 2 * NH * M_ROWS * HD;

    for (int i = p; i < 49 * 49; i += 88) Rpb[i] = rpb[h * 49 * 49 + i];

    int s[BT];
#pragma unroll
    for (int i = 0; i < BT; i++) s[i] = min(max(t0 + i - 12, 0), TT - WIN);
    const int pw0 = min(max(p - 12, 0), PP - WIN);
    const int x0  = pw0 & ~1;            // even slab base
    const bool ok0  = (pw0 == x0);       // slot 0 valid iff slab unshifted
    const bool ok25 = (pw0 != x0);       // slot 25 valid iff slab shifted
    const int rwb = x0 - p + 24;         // rpb col for slot 0

    const float* qbase = Qg + ((h * TT + t0) * PP + p) * HD;

    float o[BT][HD];
#pragma unroll
    for (int i = 0; i < BT; i++)
#pragma unroll
        for (int d = 0; d < HD; d++) o[i][d] = 0.f;
    float l[BT] = {0.f, 0.f, 0.f, 0.f};

    const int rlo = s[0];
    const int rhi = s[BT - 1] + WIN - 1;

    for (int tr = rlo; tr <= rhi; tr++) {
        __syncthreads();
        // cooperative load of one key/value t-row, transposed to [d][p]
        const float* kb = Kg + (h * TT + tr) * PP * HD;
        const float* vb = Vg + (h * TT + tr) * PP * HD;
#pragma unroll
        for (int it = 0; it < 8; it++) {
            int e  = p + it * 88;
            int pc = e >> 3;
            int dq = (e & 7) * 4;
            float4 k4 = *(const float4*)(kb + pc * HD + dq);
            float4 v4 = *(const float4*)(vb + pc * HD + dq);
            Ksh[dq + 0][pc] = k4.x; Ksh[dq + 1][pc] = k4.y;
            Ksh[dq + 2][pc] = k4.z; Ksh[dq + 3][pc] = k4.w;
            Vsh[dq + 0][pc] = v4.x; Vsh[dq + 1][pc] = v4.y;
            Vsh[dq + 2][pc] = v4.z; Vsh[dq + 3][pc] = v4.w;
        }
        __syncthreads();

        bool act[BT];
#pragma unroll
        for (int i = 0; i < BT; i++) act[i] = (tr >= s[i]) && (tr < s[i] + WIN);

#pragma unroll
        for (int half = 0; half < 2; half++) {
            const int jb = half ? 7 : 0;       // jp base (pair index)
            const int jn = half ? 6 : 7;       // pairs this half

            // ---- scores: s2[i][jp] = (q_i . K[:, x0+2(jb+jp)], q_i . K[:, ..+1])
            ull s2[BT][7];
#pragma unroll
            for (int i = 0; i < BT; i++)
#pragma unroll
                for (int jp = 0; jp < 7; jp++) s2[i][jp] = 0ull;

#pragma unroll
            for (int d4 = 0; d4 < HD / 4; d4++) {
                float4 q4[BT];
#pragma unroll
                for (int i = 0; i < BT; i++)
                    q4[i] = ((const float4*)(qbase + i * PP * HD))[d4];
#pragma unroll
                for (int dd = 0; dd < 4; dd++) {
                    const int d = d4 * 4 + dd;
                    ull qd[BT];
                    qd[0] = dup2(((const float*)&q4[0])[dd]);
                    qd[1] = dup2(((const float*)&q4[1])[dd]);
                    qd[2] = dup2(((const float*)&q4[2])[dd]);
                    qd[3] = dup2(((const float*)&q4[3])[dd]);
                    const ull* kr = (const ull*)&Ksh[d][x0] + jb;
#pragma unroll
                    for (int jp = 0; jp < 7; jp++) {
                        if (jp >= jn) break;
                        ull k2 = kr[jp];
#pragma unroll
                        for (int i = 0; i < BT; i++)
                            s2[i][jp] = fma2(qd[i], k2, s2[i][jp]);
                    }
                }
            }

            // ---- + rpb, exp (max-free), accumulate l; repack probs into s2
#pragma unroll
            for (int i = 0; i < BT; i++) {
                if (act[i]) {
                    const int base = (tr - (t0 + i) + 24) * 49 + rwb;
                    float li = 0.f;
#pragma unroll
                    for (int jp = 0; jp < 7; jp++) {
                        if (jp >= jn) break;
                        const int s0 = 2 * (jb + jp), s1 = s0 + 1;
                        float f0, f1;
                        upk2(s2[i][jp], f0, f1);
                        float g0 = (s0 != 0  || ok0)  ? __expf(f0 + Rpb[base + s0]) : 0.f;
                        float g1 = (s1 != 25 || ok25) ? __expf(f1 + Rpb[base + s1]) : 0.f;
                        li += g0 + g1;
                        s2[i][jp] = pk2(g0, g1);
                    }
                    l[i] += li;
                } else {
#pragma unroll
                    for (int jp = 0; jp < 7; jp++) s2[i][jp] = 0ull;
                }
            }

            // ---- AV accumulate (each V LDS.64 feeds 4 fma2)
#pragma unroll
            for (int d = 0; d < HD; d++) {
                const ull* vr = (const ull*)&Vsh[d][x0] + jb;
                ull acc[BT] = {0ull, 0ull, 0ull, 0ull};
#pragma unroll
                for (int jp = 0; jp < 7; jp++) {
                    if (jp >= jn) break;
                    ull v2 = vr[jp];
#pragma unroll
                    for (int i = 0; i < BT; i++)
                        acc[i] = fma2(s2[i][jp], v2, acc[i]);
                }
#pragma unroll
                for (int i = 0; i < BT; i++) {
                    float lo, hi;
                    upk2(acc[i], lo, hi);
                    o[i][d] += lo + hi;
                }
            }
        }
    }

#pragma unroll
    for (int i = 0; i < BT; i++) {
        const float inv = 1.f / l[i];
        float* outp = AO + ((t0 + i) * PP + p) * CC + h * HD;
#pragma unroll
        for (int d4 = 0; d4 < HD / 4; d4++) {
            float4 v = make_float4(o[i][d4*4] * inv, o[i][d4*4+1] * inv,
                                   o[i][d4*4+2] * inv, o[i][d4*4+3] * inv);
            *(float4*)(outp + d4 * 4) = v;
        }
    }
}

// ---------------------------------------------------------------------------
// Launch
// ---------------------------------------------------------------------------
extern "C" void kernel_launch(void* const* d_in, const int* in_sizes, int n_in,
                              void* d_out, int out_size) {
    const float* x      = (const float*)d_in[0];
    const float* cond   = (const float*)d_in[1];
    const float* mask   = (const float*)d_in[2];
    const float* lin_w  = (const float*)d_in[3];
    const float* lin_b  = (const float*)d_in[4];
    const float* qkv_w  = (const float*)d_in[5];
    const float* qkv_b  = (const float*)d_in[6];
    const float* rpb    = (const float*)d_in[7];
    const float* proj_w = (const float*)d_in[8];
    const float* proj_b = (const float*)d_in[9];
    float* out = (float*)d_out;

    float *pY, *pQKV, *pAO, *pWtLin, *pWtQkv, *pWtProj;
    cudaGetSymbolAddress((void**)&pY,      g_Y);
    cudaGetSymbolAddress((void**)&pQKV,    g_QKV);
    cudaGetSymbolAddress((void**)&pAO,     g_AO);
    cudaGetSymbolAddress((void**)&pWtLin,  g_WtLin);
    cudaGetSymbolAddress((void**)&pWtQkv,  g_WtQkv);
    cudaGetSymbolAddress((void**)&pWtProj, g_WtProj);

    // weight transposes
    transpose_w_kernel<<<(KCAT * CC + 255) / 256, 256>>>(pWtLin, lin_w, 131, KCAT, CC);
    transpose_w_kernel<<<(CC * 384 + 255) / 256, 256>>>(pWtQkv, qkv_w, CC, CC, 384);
    transpose_w_kernel<<<(CC * CC + 255) / 256, 256>>>(pWtProj, proj_w, CC, CC, CC);

    // fusion linear + relu -> Y  (concat fused into the A-tile load)
    gemm_kernel<0><<<dim3(1, M_ROWS / 128), 256>>>(x, CC, pWtLin, CC, lin_b, pY, KCAT,
                                                   cond, mask);

    for (int layer = 0; layer < 2; layer++) {
        // QKV projection (scatter into per-head layout, q pre-scaled)
        gemm_kernel<1><<<dim3(3, M_ROWS / 128), 256>>>(pY, CC, pWtQkv, 384, qkv_b, pQKV, CC,
                                                       nullptr, nullptr);
        // neighborhood attention -> AO (merged-head layout)
        attn_kernel<<<dim3(TT / BT, NH), 88>>>(pQKV, rpb, pAO);
        // output projection
        float* dst = (layer == 0) ? pY : out;
        gemm_kernel<2><<<dim3(1, M_ROWS / 128), 256>>>(pAO, CC, pWtProj, CC, proj_b, dst, CC,
                                                       nullptr, nullptr);
    }
}

// round 8
// speedup vs baseline: 1.5029x; 1.5029x over previous
#include <cuda_runtime.h>

// ---------------------------------------------------------------------------
// Problem constants
// ---------------------------------------------------------------------------
#define TT   256          // time frames (h)
#define PP   88           // pitches (w)
#define CC   128          // channels
#define NH   4            // heads
#define HD   32           // head dim
#define WIN  25           // neighborhood window
#define M_ROWS (TT*PP)    // 22528
#define KCAT 144          // padded concat K (128 + 2 + 1 -> pad to 144)
#define BT   4            // t-rows per attention block

#define QSCALE 0.17677669529663689f   // 32^-0.5

typedef unsigned long long ull;

// ---- f32x2 packed helpers (sm_103a FFMA2 is PTX-only) ----------------------
__device__ __forceinline__ ull pk2(float lo, float hi) {
    ull r; asm("mov.b64 %0,{%1,%2};" : "=l"(r) : "f"(lo), "f"(hi)); return r;
}
__device__ __forceinline__ ull dup2(float x) { return pk2(x, x); }
__device__ __forceinline__ ull fma2(ull a, ull b, ull c) {
    ull d; asm("fma.rn.f32x2 %0,%1,%2,%3;" : "=l"(d) : "l"(a), "l"(b), "l"(c)); return d;
}
__device__ __forceinline__ void upk2(ull v, float& lo, float& hi) {
    asm("mov.b64 {%0,%1},%2;" : "=f"(lo), "=f"(hi) : "l"(v));
}

// ---------------------------------------------------------------------------
// Scratch (static device globals -- no allocation allowed)
// ---------------------------------------------------------------------------
__device__ float g_Y[M_ROWS * CC];
__device__ float g_QKV[3 * NH * M_ROWS * HD];   // [i3][head][m][hd]
__device__ float g_AO[M_ROWS * CC];
__device__ float g_WtLin[KCAT * CC];            // [k][n]
__device__ float g_WtQkv[CC * 3 * CC];          // [k][n] n<384
__device__ float g_WtProj[CC * CC];             // [k][n]

// ---------------------------------------------------------------------------
// Prep kernel: transpose weights to [k][n], zero-pad k
// ---------------------------------------------------------------------------
__global__ void transpose_w_kernel(float* __restrict__ dst, const float* __restrict__ src,
                                   int Ksrc, int Kdst, int N) {
    int idx = blockIdx.x * 256 + threadIdx.x;
    if (idx >= Kdst * N) return;
    int k = idx / N, n = idx - k * N;
    dst[idx] = (k < Ksrc) ? src[n * Ksrc + k] : 0.f;
}

// ---------------------------------------------------------------------------
// Tiled SGEMM with f32x2 FMAs:  C[m][n] = sum_k A[m][k] * Bt[k][n] + bias[n]
// BM = BN = 128, BK = 16, 256 threads, 8x8 micro-tile (held as 8x4 f32x2).
// MODE 0: fusion  (A is the virtual concat [x | cond | mask | 0-pad], relu)
// MODE 1: qkv     (scatter into g_QKV layout, scale q by HD^-0.5)
// MODE 2: proj    (write row-major CC)
// ---------------------------------------------------------------------------
template <int MODE>
__global__ void __launch_bounds__(256) gemm_kernel(const float* __restrict__ A, int lda,
                                                   const float* __restrict__ Bt, int ldb,
                                                   const float* __restrict__ bias,
                                                   float* __restrict__ C, int K,
                                                   const float* __restrict__ cond,
                                                   const float* __restrict__ maskp) {
    __shared__ float As[16][132];   // [k][m], padded
    __shared__ float Bs[16][128];   // [k][n]

    const int m0 = blockIdx.y * 128;
    const int n0 = blockIdx.x * 128;
    const int tid = threadIdx.x;
    const int tx = tid & 15;
    const int ty = tid >> 4;

    ull acc2[8][4];
#pragma unroll
    for (int i = 0; i < 8; i++)
#pragma unroll
        for (int j = 0; j < 4; j++) acc2[i][j] = 0ull;

    for (int k0 = 0; k0 < K; k0 += 16) {
#pragma unroll
        for (int ii = 0; ii < 2; ii++) {
            int lin = tid + ii * 256;
            int r  = lin >> 2;            // 0..127
            int c4 = (lin & 3) * 4;       // 0,4,8,12
            int row = m0 + r;
            float4 a4;
            if (MODE == 0) {
                // virtual concat row: [x(128) | cond(2) | mask(1) | zeros]
                if (k0 < CC) {
                    a4 = *(const float4*)(A + row * CC + k0 + c4);
                } else if (c4 == 0) {
                    a4 = make_float4(cond[row * 2], cond[row * 2 + 1], maskp[row], 0.f);
                } else {
                    a4 = make_float4(0.f, 0.f, 0.f, 0.f);
                }
            } else {
                a4 = *(const float4*)(A + row * lda + k0 + c4);
            }
            As[c4 + 0][r] = a4.x; As[c4 + 1][r] = a4.y;
            As[c4 + 2][r] = a4.z; As[c4 + 3][r] = a4.w;
            int rb = lin >> 5;            // 0..15
            int cb = (lin & 31) * 4;      // 0..124
            *(float4*)&Bs[rb][cb] = *(const float4*)(Bt + (k0 + rb) * ldb + n0 + cb);
        }
        __syncthreads();
#pragma unroll
        for (int kk = 0; kk < 16; kk++) {
            float a[8];
            *(float4*)&a[0] = *(const float4*)&As[kk][ty * 8];
            *(float4*)&a[4] = *(const float4*)&As[kk][ty * 8 + 4];
            const ull* bp = (const ull*)&Bs[kk][tx * 8];
            ull b2[4] = { bp[0], bp[1], bp[2], bp[3] };
#pragma unroll
            for (int i = 0; i < 8; i++) {
                ull ad = dup2(a[i]);
#pragma unroll
                for (int j = 0; j < 4; j++)
                    acc2[i][j] = fma2(ad, b2[j], acc2[i][j]);
            }
        }
        __syncthreads();
    }

    // epilogue
#pragma unroll
    for (int i = 0; i < 8; i++) {
        int m = m0 + ty * 8 + i;
#pragma unroll
        for (int j4 = 0; j4 < 2; j4++) {
            int nbase = n0 + tx * 8 + j4 * 4;
            float vv[4];
            upk2(acc2[i][j4 * 2 + 0], vv[0], vv[1]);
            upk2(acc2[i][j4 * 2 + 1], vv[2], vv[3]);
#pragma unroll
            for (int j = 0; j < 4; j++) {
                float t = vv[j] + bias[nbase + j];
                if (MODE == 0) t = fmaxf(t, 0.f);
                if (MODE == 1 && nbase < 128) t *= QSCALE;
                vv[j] = t;
            }
            if (MODE == 1) {
                int i3   = nbase >> 7;
                int head = (nbase >> 5) & 3;
                int hd   = nbase & 31;
                *(float4*)&C[((i3 * NH + head) * M_ROWS + m) * HD + hd] = *(float4*)vv;
            } else {
                *(float4*)&C[m * CC + nbase] = *(float4*)vv;
            }
        }
    }
}

// ---------------------------------------------------------------------------
// Neighborhood attention (one head per block, BT=4 t-rows, 2 t-packed queries
// per thread -- the proven R5 structure). Max-free softmax. Window slab
// [x0, x0+25] packed as 13 f32x2 pairs, K/V via LDS.64 shared by 2 queries.
// NEW: software-pipelined K/V row loads -- global LDGs for row tr+1 are issued
// right after storing row tr to smem, so their latency hides behind row tr's
// compute instead of sitting exposed between the two __syncthreads.
// ---------------------------------------------------------------------------
__global__ void __launch_bounds__(176, 2) attn_kernel(const float* __restrict__ QKVbuf,
                                                      const float* __restrict__ rpb,
                                                      float* __restrict__ AO) {
    __shared__ float Ksh[HD][90];   // [d][p], 8B-aligned rows, conflict-free
    __shared__ float Vsh[HD][90];
    __shared__ float Rpb[49 * 49];

    const int h  = blockIdx.y;
    const int t0 = blockIdx.x * BT;
    const int p  = threadIdx.x;          // 0..87
    const int ty = threadIdx.y;          // 0..1
    const int tid = ty * PP + p;         // 0..175

    const float* Qg = QKVbuf;
    const float* Kg = QKVbuf + NH * M_ROWS * HD;
    const float* Vg = QKVbuf + 2 * NH * M_ROWS * HD;

    for (int i = tid; i < 49 * 49; i += 176) Rpb[i] = rpb[h * 49 * 49 + i];

    const int ta  = t0 + ty;             // query rows: ta, ta+2
    const int tb  = ta + 2;
    const int sa  = min(max(ta - 12, 0), TT - WIN);
    const int sb  = min(max(tb - 12, 0), TT - WIN);
    const int pw0 = min(max(p - 12, 0), PP - WIN);
    const int x0  = pw0 & ~1;            // even slab base
    const bool ok0  = (pw0 == x0);       // slot 0 valid iff slab unshifted
    const bool ok25 = (pw0 != x0);       // slot 25 valid iff slab shifted

    const float4* qa_ptr = (const float4*)(Qg + ((h * TT + ta) * PP + p) * HD);
    const float4* qb_ptr = (const float4*)(Qg + ((h * TT + tb) * PP + p) * HD);

    float oA[HD], oB[HD];
#pragma unroll
    for (int d = 0; d < HD; d++) { oA[d] = 0.f; oB[d] = 0.f; }
    float la = 0.f, lb = 0.f;

    const int rlo = min(max(t0 - 12, 0), TT - WIN);
    const int rhi = min(max(t0 + BT - 1 - 12, 0), TT - WIN) + WIN - 1;

    // per-thread chunk coordinates for the cooperative K/V row load
    int pc_[4], dq_[4];
#pragma unroll
    for (int it = 0; it < 4; it++) {
        int e = tid + it * 176;          // 0..703 (= PP*8)
        pc_[it] = e >> 3;
        dq_[it] = (e & 7) * 4;
    }

    // ---- prologue: stage row rlo in registers
    float4 k4s[4], v4s[4];
    {
        const float* kb = Kg + (h * TT + rlo) * PP * HD;
        const float* vb = Vg + (h * TT + rlo) * PP * HD;
#pragma unroll
        for (int it = 0; it < 4; it++) {
            k4s[it] = *(const float4*)(kb + pc_[it] * HD + dq_[it]);
            v4s[it] = *(const float4*)(vb + pc_[it] * HD + dq_[it]);
        }
    }

    for (int tr = rlo; tr <= rhi; tr++) {
        __syncthreads();                 // prior compute done reading smem
        // commit staged row tr (transposed to [d][p])
#pragma unroll
        for (int it = 0; it < 4; it++) {
            int pc = pc_[it], dq = dq_[it];
            Ksh[dq + 0][pc] = k4s[it].x; Ksh[dq + 1][pc] = k4s[it].y;
            Ksh[dq + 2][pc] = k4s[it].z; Ksh[dq + 3][pc] = k4s[it].w;
            Vsh[dq + 0][pc] = v4s[it].x; Vsh[dq + 1][pc] = v4s[it].y;
            Vsh[dq + 2][pc] = v4s[it].z; Vsh[dq + 3][pc] = v4s[it].w;
        }
        // issue LDGs for row tr+1 -- latency hides behind this row's compute
        if (tr < rhi) {
            const float* kb = Kg + (h * TT + tr + 1) * PP * HD;
            const float* vb = Vg + (h * TT + tr + 1) * PP * HD;
#pragma unroll
            for (int it = 0; it < 4; it++) {
                k4s[it] = *(const float4*)(kb + pc_[it] * HD + dq_[it]);
                v4s[it] = *(const float4*)(vb + pc_[it] * HD + dq_[it]);
            }
        }
        __syncthreads();                 // smem row tr visible

        const bool actA = (tr >= sa) && (tr < sa + WIN);
        const bool actB = (tr >= sb) && (tr < sb + WIN);
        if (!(actA || actB)) continue;

        // ---- scores: sX2[jp] = (q . K[:, x0+2jp], q . K[:, x0+2jp+1])
        ull sA2[13], sB2[13];
#pragma unroll
        for (int jp = 0; jp < 13; jp++) { sA2[jp] = 0ull; sB2[jp] = 0ull; }

#pragma unroll
        for (int d4 = 0; d4 < HD / 4; d4++) {
            float4 qa4 = qa_ptr[d4];
            float4 qb4 = qb_ptr[d4];
            const float* qaf = (const float*)&qa4;
            const float* qbf = (const float*)&qb4;
#pragma unroll
            for (int dd = 0; dd < 4; dd++) {
                const int d = d4 * 4 + dd;
                ull qaD = dup2(qaf[dd]);
                ull qbD = dup2(qbf[dd]);
                const ull* kr = (const ull*)&Ksh[d][x0];
#pragma unroll
                for (int jp = 0; jp < 13; jp++) {
                    ull k2 = kr[jp];
                    sA2[jp] = fma2(qaD, k2, sA2[jp]);
                    sB2[jp] = fma2(qbD, k2, sB2[jp]);
                }
            }
        }

        // ---- + rpb, exp (max-free), accumulate l; repack probs into sX2
        const int baseA = (tr - ta + 24) * 49 + (x0 - p + 24);
        const int baseB = (tr - tb + 24) * 49 + (x0 - p + 24);
#pragma unroll
        for (int jp = 0; jp < 13; jp++) {
            const int s0 = 2 * jp, s1 = 2 * jp + 1;
            const bool v0 = (s0 != 0 || ok0);
            const bool v1 = (s1 != 25 || ok25);
            float f0, f1, g0, g1;
            upk2(sA2[jp], f0, f1);
            g0 = (actA && v0) ? __expf(f0 + Rpb[baseA + s0]) : 0.f;
            g1 = (actA && v1) ? __expf(f1 + Rpb[baseA + s1]) : 0.f;
            la += g0 + g1;
            sA2[jp] = pk2(g0, g1);
            upk2(sB2[jp], f0, f1);
            g0 = (actB && v0) ? __expf(f0 + Rpb[baseB + s0]) : 0.f;
            g1 = (actB && v1) ? __expf(f1 + Rpb[baseB + s1]) : 0.f;
            lb += g0 + g1;
            sB2[jp] = pk2(g0, g1);
        }

        // ---- AV accumulate (V LDS.64 shared by both queries)
#pragma unroll
        for (int d = 0; d < HD; d++) {
            const ull* vr = (const ull*)&Vsh[d][x0];
            ull aA = 0ull, aB = 0ull;
#pragma unroll
            for (int jp = 0; jp < 13; jp++) {
                ull v2 = vr[jp];
                aA = fma2(sA2[jp], v2, aA);
                aB = fma2(sB2[jp], v2, aB);
            }
            float lo, hi;
            upk2(aA, lo, hi); oA[d] += lo + hi;
            upk2(aB, lo, hi); oB[d] += lo + hi;
        }
    }

    const float inva = 1.f / la;
    const float invb = 1.f / lb;
    float* outa = AO + (ta * PP + p) * CC + h * HD;
    float* outb = AO + (tb * PP + p) * CC + h * HD;
#pragma unroll
    for (int d4 = 0; d4 < HD / 4; d4++) {
        float4 va = make_float4(oA[d4*4] * inva, oA[d4*4+1] * inva,
                                oA[d4*4+2] * inva, oA[d4*4+3] * inva);
        float4 vb = make_float4(oB[d4*4] * invb, oB[d4*4+1] * invb,
                                oB[d4*4+2] * invb, oB[d4*4+3] * invb);
        *(float4*)(outa + d4 * 4) = va;
        *(float4*)(outb + d4 * 4) = vb;
    }
}

// ---------------------------------------------------------------------------
// Launch
// ---------------------------------------------------------------------------
extern "C" void kernel_launch(void* const* d_in, const int* in_sizes, int n_in,
                              void* d_out, int out_size) {
    const float* x      = (const float*)d_in[0];
    const float* cond   = (const float*)d_in[1];
    const float* mask   = (const float*)d_in[2];
    const float* lin_w  = (const float*)d_in[3];
    const float* lin_b  = (const float*)d_in[4];
    const float* qkv_w  = (const float*)d_in[5];
    const float* qkv_b  = (const float*)d_in[6];
    const float* rpb    = (const float*)d_in[7];
    const float* proj_w = (const float*)d_in[8];
    const float* proj_b = (const float*)d_in[9];
    float* out = (float*)d_out;

    float *pY, *pQKV, *pAO, *pWtLin, *pWtQkv, *pWtProj;
    cudaGetSymbolAddress((void**)&pY,      g_Y);
    cudaGetSymbolAddress((void**)&pQKV,    g_QKV);
    cudaGetSymbolAddress((void**)&pAO,     g_AO);
    cudaGetSymbolAddress((void**)&pWtLin,  g_WtLin);
    cudaGetSymbolAddress((void**)&pWtQkv,  g_WtQkv);
    cudaGetSymbolAddress((void**)&pWtProj, g_WtProj);

    // weight transposes
    transpose_w_kernel<<<(KCAT * CC + 255) / 256, 256>>>(pWtLin, lin_w, 131, KCAT, CC);
    transpose_w_kernel<<<(CC * 384 + 255) / 256, 256>>>(pWtQkv, qkv_w, CC, CC, 384);
    transpose_w_kernel<<<(CC * CC + 255) / 256, 256>>>(pWtProj, proj_w, CC, CC, CC);

    // fusion linear + relu -> Y  (concat fused into the A-tile load)
    gemm_kernel<0><<<dim3(1, M_ROWS / 128), 256>>>(x, CC, pWtLin, CC, lin_b, pY, KCAT,
                                                   cond, mask);

    for (int layer = 0; layer < 2; layer++) {
        // QKV projection (scatter into per-head layout, q pre-scaled)
        gemm_kernel<1><<<dim3(3, M_ROWS / 128), 256>>>(pY, CC, pWtQkv, 384, qkv_b, pQKV, CC,
                                                       nullptr, nullptr);
        // neighborhood attention -> AO (merged-head layout)
        attn_kernel<<<dim3(TT / BT, NH), dim3(PP, 2)>>>(pQKV, rpb, pAO);
        // output projection
        float* dst = (layer == 0) ? pY : out;
        gemm_kernel<2><<<dim3(1, M_ROWS / 128), 256>>>(pAO, CC, pWtProj, CC, proj_b, dst, CC,
                                                       nullptr, nullptr);
    }
}